// round 13
// baseline (speedup 1.0000x reference)
#include <cuda_runtime.h>

// TT-embedding — single persistent kernel with in-kernel token sort by pq.
//   core0: (1,8,40,16)    A[x][p][b]     idx = x*640 + p*16 + b
//   core1: (16,8,32,16)   M[b][y][q][c]  idx = b*4096 + y*512 + q*16 + c
//   core2: (16,16,25,1)   C[c][z][r]     idx = c*400 + z*25 + r
//   id -> p = id/800, q = (id%800)/25, r = id%25
//   out[tok][xy*16+z] = sum_c s[pq][c][xy] * c2t[r][c][z]
//
// A0: smem c2t + id-width sniff; blocks 0-4 zero hist. A1: build permuted
//     s rows g_s[pq][c][a*8+m].                          -- barrier --
// A2: histogram tokens by pq (atomics).                  -- barrier --
// A3: block 0 prefix-sums hist -> g_off (reads __ldcg).  -- barrier --
// A4: scatter: g_sorted[pos] = tok (atomic ticket).      -- barrier --
// B:  warps take CONTIGUOUS chunks of g_sorted (~4.6 tokens, mostly same pq
//     -> s-row LDGs hit L1); R11-proven FMA body; next-token prefetch.
//
// GRID=444 = 148 SMs x 3; launch_bounds(256,3): regs<=85, smem ~36KB x 3.
// Epoch-ticket barrier is monotonic -> CUDA-graph-replay safe. All sort
// buffers are rewritten every launch (hist re-zeroed before use).

#define NTOK  16384
#define GRID  444
#define NW    (GRID * 8)
#define NROWS 1280
typedef unsigned long long ull;

__device__ float g_s[NROWS * 1024];
__device__ int g_hist[NROWS];
__device__ int g_off[NROWS];
__device__ unsigned short g_sorted[NTOK];
__device__ unsigned g_bar;   // monotonic epoch counter (never reset)

__device__ __forceinline__ void grid_barrier(int t) {
    __threadfence();
    __syncthreads();
    if (t == 0) {
        unsigned k = atomicAdd(&g_bar, 1u);
        unsigned target = (k / GRID + 1u) * GRID;
        while (atomicAdd(&g_bar, 0u) < target) __nanosleep(32);
    }
    __syncthreads();
}

__global__ __launch_bounds__(256, 3) void tt_fused(const float* __restrict__ c0,
                                                   const float* __restrict__ c1,
                                                   const float* __restrict__ c2,
                                                   const int* __restrict__ ids,
                                                   float* __restrict__ out) {
    __shared__ __align__(16) float Cs[6400];   // c2t [r][c][z]
    __shared__ float sA[128];                  // [x][b]
    __shared__ float sM[2048];                 // [b][y][c]
    __shared__ int sc[256];                    // prefix-scan scratch
    __shared__ int sIds64;

    int t = threadIdx.x;
    int bid = blockIdx.x;

    // ---- A0: c2 transpose into smem; zero hist; sniff id width ----
    for (int i = t; i < 6400; i += 256) {
        int r = i >> 8, cz = i & 255;
        int cc = cz >> 4, z = cz & 15;
        Cs[i] = c2[cc * 400 + z * 25 + r];
    }
    if (bid < 5) {
        int i = bid * 256 + t;
        if (i < NROWS) g_hist[i] = 0;
    }
    if (t == 0) {
        int ored = 0;
#pragma unroll
        for (int i = 0; i < 32; ++i) ored |= ids[2 * i + 1];
        sIds64 = (ored == 0) ? 1 : 0;
    }

    // ---- A1: build this block's s rows (permuted layout) ----
    for (int pq = bid; pq < NROWS; pq += GRID) {
        int p = pq >> 5, q = pq & 31;
        __syncthreads();
        if (t < 128) {
            int x = t >> 4, b = t & 15;
            sA[t] = c0[x * 640 + p * 16 + b];
        }
        for (int i = t; i < 2048; i += 256) {
            int b = i >> 7, y = (i >> 4) & 7, cc = i & 15;
            sM[i] = c1[b * 4096 + y * 512 + q * 16 + cc];
        }
        __syncthreads();
        for (int o = t; o < 1024; o += 256) {
            int cc = o >> 6, xy = o & 63;
            int x = xy >> 3, y = xy & 7;
            float acc = 0.f;
#pragma unroll
            for (int b = 0; b < 16; ++b)
                acc += sA[x * 16 + b] * sM[b * 128 + y * 16 + cc];
            g_s[pq * 1024 + cc * 64 + ((xy & 7) << 3) + (xy >> 3)] = acc;
        }
    }

    int ids64 = sIds64;   // sIds64 written before first __syncthreads above

    grid_barrier(t);   // hist zeroed, s built

    // ---- A2: histogram tokens by pq ----
    {
        int tok = bid * 256 + t;
        if (tok < NTOK) {
            int id = ids64 ? __ldg(ids + 2 * tok) : __ldg(ids + tok);
            atomicAdd(&g_hist[id / 25], 1);   // pq = p*32+q = id/25... NO:
        }
    }
    grid_barrier(t);

    // ---- A3: block 0 exclusive-prefix hist -> g_off ----
    if (bid == 0) {
        int v[5], s = 0;
#pragma unroll
        for (int k = 0; k < 5; ++k) { v[k] = __ldcg(&g_hist[t * 5 + k]); s += v[k]; }
        sc[t] = s;
        __syncthreads();
        for (int off = 1; off < 256; off <<= 1) {
            int x = (t >= off) ? sc[t - off] : 0;
            __syncthreads();
            sc[t] += x;
            __syncthreads();
        }
        int excl = sc[t] - s;
#pragma unroll
        for (int k = 0; k < 5; ++k) { g_off[t * 5 + k] = excl; excl += v[k]; }
    }
    grid_barrier(t);

    // ---- A4: scatter tokens into sorted order ----
    {
        int tok = bid * 256 + t;
        if (tok < NTOK) {
            int id = ids64 ? __ldg(ids + 2 * tok) : __ldg(ids + tok);
            int pq = (id / 800) * 32 + (id % 800) / 25;
            int pos = atomicAdd(&g_off[pq], 1);
            g_sorted[pos] = (unsigned short)tok;
        }
    }
    grid_barrier(t);

    // ---- B: gather over sorted tokens, contiguous warp chunks ----
    int lane = t & 31, warp = t >> 5;
    int a = lane >> 2, zq = lane & 3;
    int wg = bid * 8 + warp;
    int start = (int)(((long long)wg * NTOK) / NW);
    int end = (int)(((long long)(wg + 1) * NTOK) / NW);

    if (start < end) {
        int tok_n = g_sorted[start];
        int id_n = ids64 ? __ldg(ids + 2 * tok_n) : __ldg(ids + tok_n);

        for (int i = start; i < end; ++i) {
            int tok = tok_n;
            int id = id_n;
            if (i + 1 < end) {                 // prefetch next token's id
                tok_n = g_sorted[i + 1];
                id_n = ids64 ? __ldg(ids + 2 * tok_n) : __ldg(ids + tok_n);
            }

            int p = id / 800;
            int rem = id - p * 800;
            int q = rem / 25;
            int r = rem - q * 25;

            const float4* sp = reinterpret_cast<const float4*>(
                g_s + (p * 32 + q) * 1024 + a * 8);
            const ulonglong2* cr =
                reinterpret_cast<const ulonglong2*>(Cs + r * 256 + zq * 4);

            ull acc0[8], acc1[8];
#pragma unroll
            for (int m = 0; m < 8; ++m) { acc0[m] = 0ull; acc1[m] = 0ull; }

#pragma unroll
            for (int c = 0; c < 16; ++c) {
                float4 sv0 = sp[c * 16];       // m = 0..3
                float4 sv1 = sp[c * 16 + 1];   // m = 4..7
                ulonglong2 cv = cr[c * 4];     // lane's 16B of c2t[r][c]

                ull b0, b1, b2, b3, b4, b5, b6, b7;
                asm("mov.b64 %0,{%1,%1};" : "=l"(b0) : "f"(sv0.x));
                asm("mov.b64 %0,{%1,%1};" : "=l"(b1) : "f"(sv0.y));
                asm("mov.b64 %0,{%1,%1};" : "=l"(b2) : "f"(sv0.z));
                asm("mov.b64 %0,{%1,%1};" : "=l"(b3) : "f"(sv0.w));
                asm("mov.b64 %0,{%1,%1};" : "=l"(b4) : "f"(sv1.x));
                asm("mov.b64 %0,{%1,%1};" : "=l"(b5) : "f"(sv1.y));
                asm("mov.b64 %0,{%1,%1};" : "=l"(b6) : "f"(sv1.z));
                asm("mov.b64 %0,{%1,%1};" : "=l"(b7) : "f"(sv1.w));

                asm("fma.rn.f32x2 %0,%1,%2,%0;" : "+l"(acc0[0]) : "l"(b0), "l"(cv.x));
                asm("fma.rn.f32x2 %0,%1,%2,%0;" : "+l"(acc1[0]) : "l"(b0), "l"(cv.y));
                asm("fma.rn.f32x2 %0,%1,%2,%0;" : "+l"(acc0[1]) : "l"(b1), "l"(cv.x));
                asm("fma.rn.f32x2 %0,%1,%2,%0;" : "+l"(acc1[1]) : "l"(b1), "l"(cv.y));
                asm("fma.rn.f32x2 %0,%1,%2,%0;" : "+l"(acc0[2]) : "l"(b2), "l"(cv.x));
                asm("fma.rn.f32x2 %0,%1,%2,%0;" : "+l"(acc1[2]) : "l"(b2), "l"(cv.y));
                asm("fma.rn.f32x2 %0,%1,%2,%0;" : "+l"(acc0[3]) : "l"(b3), "l"(cv.x));
                asm("fma.rn.f32x2 %0,%1,%2,%0;" : "+l"(acc1[3]) : "l"(b3), "l"(cv.y));
                asm("fma.rn.f32x2 %0,%1,%2,%0;" : "+l"(acc0[4]) : "l"(b4), "l"(cv.x));
                asm("fma.rn.f32x2 %0,%1,%2,%0;" : "+l"(acc1[4]) : "l"(b4), "l"(cv.y));
                asm("fma.rn.f32x2 %0,%1,%2,%0;" : "+l"(acc0[5]) : "l"(b5), "l"(cv.x));
                asm("fma.rn.f32x2 %0,%1,%2,%0;" : "+l"(acc1[5]) : "l"(b5), "l"(cv.y));
                asm("fma.rn.f32x2 %0,%1,%2,%0;" : "+l"(acc0[6]) : "l"(b6), "l"(cv.x));
                asm("fma.rn.f32x2 %0,%1,%2,%0;" : "+l"(acc1[6]) : "l"(b6), "l"(cv.y));
                asm("fma.rn.f32x2 %0,%1,%2,%0;" : "+l"(acc0[7]) : "l"(b7), "l"(cv.x));
                asm("fma.rn.f32x2 %0,%1,%2,%0;" : "+l"(acc1[7]) : "l"(b7), "l"(cv.y));
            }

            float* obase = out + (size_t)tok * 1024 + lane * 4;
#pragma unroll
            for (int m = 0; m < 8; ++m)
                *reinterpret_cast<ulonglong2*>(obase + m * 128) =
                    make_ulonglong2(acc0[m], acc1[m]);
        }
    }
}

// ---------------------------------------------------------------------------
extern "C" void kernel_launch(void* const* d_in, const int* in_sizes, int n_in,
                              void* d_out, int out_size) {
    const float* core0 = (const float*)d_in[0];
    const float* core1 = (const float*)d_in[1];
    const float* core2 = (const float*)d_in[2];
    const int*   ids   = (const int*)d_in[3];
    float* out = (float*)d_out;

    tt_fused<<<GRID, 256>>>(core0, core1, core2, ids, out);
}

// round 15
// speedup vs baseline: 1.1490x; 1.1490x over previous
#include <cuda_runtime.h>

// TT-embedding — single persistent kernel, warp-PAIR per token.
//   core0: (1,8,40,16)    A[x][p][b]     idx = x*640 + p*16 + b
//   core1: (16,8,32,16)   M[b][y][q][c]  idx = b*4096 + y*512 + q*16 + c
//   core2: (16,16,25,1)   C[c][z][r]     idx = c*400 + z*25 + r
//   id -> p = id/800, q = (id%800)/25, r = id%25
//   out[tok][xy*16+z] = sum_c s[pq][c][xy] * c2t[r][c][z],  xy = m*8+a
//
// Phase A: smem c2t Cs[r][c][z]; build permuted s rows g_s[pq][c][a*8+m].
// Grid barrier (epoch tickets, monotonic -> graph-replay safe).
// Phase B: TWO warps per token (h = parity): lane owns a=lane>>2,
//   zq=lane&3, m in {4h..4h+3}. 16 regs of accumulators -> 4 blocks/SM.
//   Per c per lane: 1 LDG.128 (s quad, 1 wavefront/warp) + 1 LDS.128 +
//   4 pair-broadcasts + 8 FFMA2.
//
// GRID=592 = 148 SMs x 4; __launch_bounds__(256,4): regs<=64,
// smem ~35KB x 4 = 140KB <= 228KB -> co-resident, barrier cannot deadlock.

#define NTOK  16384
#define GRID  592
#define NWP   (GRID * 4)    // warp-pairs
#define NROWS 1280
typedef unsigned long long ull;

__device__ float g_s[NROWS * 1024];
__device__ unsigned g_bar;   // monotonic epoch counter (never reset)

__global__ __launch_bounds__(256, 4) void tt_fused(const float* __restrict__ c0,
                                                   const float* __restrict__ c1,
                                                   const float* __restrict__ c2,
                                                   const int* __restrict__ ids,
                                                   float* __restrict__ out) {
    __shared__ __align__(16) float Cs[6400];   // c2t [r][c][z]
    __shared__ float sA[128];                  // [x][b]
    __shared__ float sM[2048];                 // [b][y][c]
    __shared__ int sIds64;

    int t = threadIdx.x;
    int bid = blockIdx.x;

    // ---- Phase A0: c2 transpose into this block's smem ----
    for (int i = t; i < 6400; i += 256) {
        int r = i >> 8, cz = i & 255;
        int cc = cz >> 4, z = cz & 15;
        Cs[i] = c2[cc * 400 + z * 25 + r];
    }
    if (t == 0) {
        int ored = 0;
#pragma unroll
        for (int i = 0; i < 32; ++i) ored |= ids[2 * i + 1];
        sIds64 = (ored == 0) ? 1 : 0;
    }

    // ---- Phase A1: build this block's s rows (permuted layout) ----
    for (int pq = bid; pq < NROWS; pq += GRID) {
        int p = pq >> 5, q = pq & 31;
        __syncthreads();
        if (t < 128) {
            int x = t >> 4, b = t & 15;
            sA[t] = c0[x * 640 + p * 16 + b];
        }
        for (int i = t; i < 2048; i += 256) {
            int b = i >> 7, y = (i >> 4) & 7, cc = i & 15;
            sM[i] = c1[b * 4096 + y * 512 + q * 16 + cc];
        }
        __syncthreads();
        for (int o = t; o < 1024; o += 256) {
            int cc = o >> 6, xy = o & 63;
            int x = xy >> 3, y = xy & 7;
            float acc = 0.f;
#pragma unroll
            for (int b = 0; b < 16; ++b)
                acc += sA[x * 16 + b] * sM[b * 128 + y * 16 + cc];
            g_s[pq * 1024 + cc * 64 + ((xy & 7) << 3) + (xy >> 3)] = acc;
        }
    }

    int ids64 = sIds64;

    // ---- grid-wide barrier (epoch tickets; replay-safe) ----
    __threadfence();
    __syncthreads();
    if (t == 0) {
        unsigned k = atomicAdd(&g_bar, 1u);
        unsigned target = (k / GRID + 1u) * GRID;
        while (atomicAdd(&g_bar, 0u) < target) __nanosleep(32);
    }
    __syncthreads();
    __threadfence();

    // ---- Phase B: gather, warp-pair per token ----
    int lane = t & 31, warp = t >> 5;
    int a = lane >> 2, zq = lane & 3;
    int gw = bid * 8 + warp;
    int wp = gw >> 1;        // warp-pair id
    int h = gw & 1;          // m-half: h=0 -> m 0..3, h=1 -> m 4..7

    for (int tok = wp; tok < NTOK; tok += NWP) {
        int id = ids64 ? __ldg(ids + 2 * tok) : __ldg(ids + tok);
        int p = id / 800;
        int rem = id - p * 800;
        int q = rem / 25;
        int r = rem - q * 25;

        // lane's m-quad of the s row: floats [a*8 + h*4 .. +3], per c stride 64
        const float4* sp = reinterpret_cast<const float4*>(
            g_s + (p * 32 + q) * 1024 + a * 8 + h * 4);
        const ulonglong2* cr =
            reinterpret_cast<const ulonglong2*>(Cs + r * 256 + zq * 4);

        ull acc0[4], acc1[4];   // [m within quad], z pairs (4zq,4zq+1),(4zq+2,4zq+3)
#pragma unroll
        for (int m = 0; m < 4; ++m) { acc0[m] = 0ull; acc1[m] = 0ull; }

#pragma unroll
        for (int c = 0; c < 16; ++c) {
            float4 sv = sp[c * 16];        // this lane's 4 m values
            ulonglong2 cv = cr[c * 4];     // lane's 16B of c2t[r][c]

            ull b0, b1, b2, b3;
            asm("mov.b64 %0,{%1,%1};" : "=l"(b0) : "f"(sv.x));
            asm("mov.b64 %0,{%1,%1};" : "=l"(b1) : "f"(sv.y));
            asm("mov.b64 %0,{%1,%1};" : "=l"(b2) : "f"(sv.z));
            asm("mov.b64 %0,{%1,%1};" : "=l"(b3) : "f"(sv.w));

            asm("fma.rn.f32x2 %0,%1,%2,%0;" : "+l"(acc0[0]) : "l"(b0), "l"(cv.x));
            asm("fma.rn.f32x2 %0,%1,%2,%0;" : "+l"(acc1[0]) : "l"(b0), "l"(cv.y));
            asm("fma.rn.f32x2 %0,%1,%2,%0;" : "+l"(acc0[1]) : "l"(b1), "l"(cv.x));
            asm("fma.rn.f32x2 %0,%1,%2,%0;" : "+l"(acc1[1]) : "l"(b1), "l"(cv.y));
            asm("fma.rn.f32x2 %0,%1,%2,%0;" : "+l"(acc0[2]) : "l"(b2), "l"(cv.x));
            asm("fma.rn.f32x2 %0,%1,%2,%0;" : "+l"(acc1[2]) : "l"(b2), "l"(cv.y));
            asm("fma.rn.f32x2 %0,%1,%2,%0;" : "+l"(acc0[3]) : "l"(b3), "l"(cv.x));
            asm("fma.rn.f32x2 %0,%1,%2,%0;" : "+l"(acc1[3]) : "l"(b3), "l"(cv.y));
        }

        // store 4 m rows: out[tok][ (m*8+a)*16 + z ], m = h*4 + k
        float* obase = out + (size_t)tok * 1024 + (h * 4) * 128 + a * 16 + zq * 4;
#pragma unroll
        for (int k = 0; k < 4; ++k)
            *reinterpret_cast<ulonglong2*>(obase + k * 128) =
                make_ulonglong2(acc0[k], acc1[k]);
    }
}

// ---------------------------------------------------------------------------
extern "C" void kernel_launch(void* const* d_in, const int* in_sizes, int n_in,
                              void* d_out, int out_size) {
    const float* core0 = (const float*)d_in[0];
    const float* core1 = (const float*)d_in[1];
    const float* core2 = (const float*)d_in[2];
    const int*   ids   = (const int*)d_in[3];
    float* out = (float*)d_out;

    tt_fused<<<GRID, 256>>>(core0, core1, core2, ids, out);
}